// round 2
// baseline (speedup 1.0000x reference)
#include <cuda_runtime.h>

#define D   128
#define NG  16384
#define MAXN 524288
#define MAXE 1048576

typedef unsigned long long u64;

// ---------------- device scratch (no allocations allowed) ----------------
__device__ int   d_is64[2];                      // [0]=batch is int64, [1]=edge_index is int64
__device__ float g_g  [(size_t)NG * D];          // pooled graph means  [G,128]
__device__ float g_gW2[(size_t)NG * D];          // b_node + g @ Wn2    [G,128]
__device__ float g_A  [(size_t)MAXN * D];        // node_rep @ We1      [N,128]
__device__ float g_B  [(size_t)MAXN * D];        // node_rep @ We2      [N,128]

// ---------------- helpers ----------------
__device__ __forceinline__ u64 pack2(float x, float y) {
    u64 r; asm("mov.b64 %0, {%1,%2};" : "=l"(r) : "f"(x), "f"(y)); return r;
}
__device__ __forceinline__ float2 unpack2(u64 v) {
    float2 f; asm("mov.b64 {%0,%1}, %2;" : "=f"(f.x), "=f"(f.y) : "l"(v)); return f;
}
// packed fp32 FMA (FFMA2) — sm_100+/sm_103a
__device__ __forceinline__ u64 ffma2(u64 a, u64 b, u64 c) {
    u64 d; asm("fma.rn.f32x2 %0, %1, %2, %3;" : "=l"(d) : "l"(a), "l"(b), "l"(c)); return d;
}

__device__ __forceinline__ long ldx(const void* p, long i, int is64) {
    if (is64) return (long)__ldg((const long long*)p + i);
    return (long)__ldg((const int*)p + i);
}

// mish(x) = x * tanh(softplus(x)) = x * ((1+e^x)^2 - 1) / ((1+e^x)^2 + 1)
__device__ __forceinline__ float mish1(float x) {
    float t = __expf(x);
    float u = t * t + 2.f * t;           // (1+t)^2 - 1
    float r = x * (u / (u + 2.f));
    return (x > 20.f) ? x : r;
}
__device__ __forceinline__ float4 mish4(float4 v) {
    v.x = mish1(v.x); v.y = mish1(v.y); v.z = mish1(v.z); v.w = mish1(v.w);
    return v;
}

// ---------------- kernel 0: dtype detection (int64 vs int32 indices) ----------------
// int64 little-endian non-negative values < 2^31 have zero high words at odd u32
// indices. batch is sorted (last value ~16383, nonzero if int32); edge values
// are random in [0, 524288) (prob of 4 specific zeros ~0).
__global__ void k_detect(const unsigned* __restrict__ b, int nb, const unsigned* __restrict__ e) {
    if (threadIdx.x == 0 && blockIdx.x == 0) {
        d_is64[0] = (b[nb - 1] == 0u && b[nb - 3] == 0u) ? 1 : 0;
        d_is64[1] = (e[1] == 0u && e[3] == 0u && e[5] == 0u && e[7] == 0u) ? 1 : 0;
    }
}

// ---------------- kernel 1: segment mean (batch is sorted -> binary search) ----------------
__global__ void k_pool(const float* __restrict__ x, const void* __restrict__ batch, int N) {
    int gid = blockIdx.x;          // one block per graph
    int t = threadIdx.x;           // 128 threads = one column each
    int is64 = d_is64[0];
    __shared__ int s_lo, s_hi;
    if (t == 0) {
        int lo = 0, hi = N;
        while (lo < hi) { int m = (lo + hi) >> 1; if (ldx(batch, m, is64) < (long)gid) lo = m + 1; else hi = m; }
        s_lo = lo;
        hi = N;
        while (lo < hi) { int m = (lo + hi) >> 1; if (ldx(batch, m, is64) < (long)gid + 1) lo = m + 1; else hi = m; }
        s_hi = lo;
    }
    __syncthreads();
    int lo = s_lo, hi = s_hi;
    float sum = 0.f;
    for (int i = lo; i < hi; i++) sum += __ldg(&x[(size_t)i * D + t]);
    float cnt = (float)(hi - lo);
    g_g[(size_t)gid * D + t] = sum / fmaxf(cnt, 1.f);
}

// ---------------- kernel 2: gW2 = b_node + g@Wn2 ; graph_rep = b_pool + g@W_pool ----------------
__global__ __launch_bounds__(256) void k_graphmm(
    const float* __restrict__ Wn, const float* __restrict__ bn,
    const float* __restrict__ Wp, const float* __restrict__ bp,
    float* __restrict__ graph_out, int G)
{
    __shared__ float gs[64][D];
    int lane = threadIdx.x & 31, wy = threadIdx.x >> 5;
    int c = lane * 4;

    for (int row0 = blockIdx.x * 64; row0 < G; row0 += gridDim.x * 64) {
        #pragma unroll
        for (int j = 0; j < 8; j++) {
            int r = wy + 8 * j;
            *(float4*)&gs[r][c] = *(const float4*)&g_g[(size_t)(row0 + r) * D + c];
        }
        __syncwarp();

        float4 acc2[8], accP[8];
        float4 bn4 = __ldg((const float4*)&bn[c]);
        float4 bp4 = __ldg((const float4*)&bp[c]);
        #pragma unroll
        for (int j = 0; j < 8; j++) { acc2[j] = bn4; accP[j] = bp4; }

        for (int k = 0; k < D; k++) {
            float4 w2 = __ldg((const float4*)&Wn[(size_t)(D + k) * D + c]);
            float4 wp = __ldg((const float4*)&Wp[(size_t)k * D + c]);
            #pragma unroll
            for (int j = 0; j < 8; j++) {
                float a = gs[wy + 8 * j][k];
                acc2[j].x = fmaf(a, w2.x, acc2[j].x); acc2[j].y = fmaf(a, w2.y, acc2[j].y);
                acc2[j].z = fmaf(a, w2.z, acc2[j].z); acc2[j].w = fmaf(a, w2.w, acc2[j].w);
                accP[j].x = fmaf(a, wp.x, accP[j].x); accP[j].y = fmaf(a, wp.y, accP[j].y);
                accP[j].z = fmaf(a, wp.z, accP[j].z); accP[j].w = fmaf(a, wp.w, accP[j].w);
            }
        }
        #pragma unroll
        for (int j = 0; j < 8; j++) {
            size_t row = row0 + wy + 8 * j;
            *(float4*)&g_gW2[row * D + c] = acc2[j];
            *(float4*)&graph_out[row * D + c] = accP[j];
        }
        __syncwarp();
    }
}

// ---------------- kernel 3: fused node MLP + A/B precompute + self-edge ----------------
// Warp-autonomous: warp wy owns rows {wy, wy+8, ..., wy+56} of a 64-row tile.
// Packed fp32 (fma.rn.f32x2) doubles fp32 FMA throughput.
__global__ __launch_bounds__(256) void k_fuse(
    const float* __restrict__ x, const void* __restrict__ batch,
    const float* __restrict__ Wn, const float* __restrict__ We,
    const float* __restrict__ be,
    float* __restrict__ node_out, float* __restrict__ self_out, int N)
{
    __shared__ float xs[64][D];
    int lane = threadIdx.x & 31, wy = threadIdx.x >> 5;
    int c = lane * 4;
    int is64 = d_is64[0];

    for (int row0 = blockIdx.x * 64; row0 < N; row0 += gridDim.x * 64) {
        // load x tile (each warp loads its own rows)
        #pragma unroll
        for (int j = 0; j < 8; j++) {
            int r = wy + 8 * j;
            *(float4*)&xs[r][c] = __ldg((const float4*)&x[(size_t)(row0 + r) * D + c]);
        }
        __syncwarp();

        // ---- phase 1: nr = mish(x @ Wn1 + gW2[batch])  (gW2 includes b_node) ----
        u64 acc0[8], acc1[8];
        #pragma unroll
        for (int j = 0; j < 8; j++) {
            long r = row0 + wy + 8 * j;
            long b = ldx(batch, r, is64);
            ulonglong2 gv = __ldg((const ulonglong2*)(g_gW2 + (size_t)b * D + c));
            acc0[j] = gv.x; acc1[j] = gv.y;
        }
        for (int k0 = 0; k0 < D; k0 += 4) {
            ulonglong2 w0 = __ldg((const ulonglong2*)(Wn + (size_t)(k0 + 0) * D + c));
            ulonglong2 w1 = __ldg((const ulonglong2*)(Wn + (size_t)(k0 + 1) * D + c));
            ulonglong2 w2 = __ldg((const ulonglong2*)(Wn + (size_t)(k0 + 2) * D + c));
            ulonglong2 w3 = __ldg((const ulonglong2*)(Wn + (size_t)(k0 + 3) * D + c));
            #pragma unroll
            for (int j = 0; j < 8; j++) {
                float4 a4 = *(const float4*)&xs[wy + 8 * j][k0];
                u64 aa;
                aa = pack2(a4.x, a4.x); acc0[j] = ffma2(aa, w0.x, acc0[j]); acc1[j] = ffma2(aa, w0.y, acc1[j]);
                aa = pack2(a4.y, a4.y); acc0[j] = ffma2(aa, w1.x, acc0[j]); acc1[j] = ffma2(aa, w1.y, acc1[j]);
                aa = pack2(a4.z, a4.z); acc0[j] = ffma2(aa, w2.x, acc0[j]); acc1[j] = ffma2(aa, w2.y, acc1[j]);
                aa = pack2(a4.w, a4.w); acc0[j] = ffma2(aa, w3.x, acc0[j]); acc1[j] = ffma2(aa, w3.y, acc1[j]);
            }
        }
        float4 nr[8];
        #pragma unroll
        for (int j = 0; j < 8; j++) {
            float2 lo = unpack2(acc0[j]), hi = unpack2(acc1[j]);
            float4 v = make_float4(mish1(lo.x), mish1(lo.y), mish1(hi.x), mish1(hi.y));
            nr[j] = v;
            size_t row = row0 + wy + 8 * j;
            *(float4*)&node_out[row * D + c] = v;
        }
        __syncwarp();
        #pragma unroll
        for (int j = 0; j < 8; j++) *(float4*)&xs[wy + 8 * j][c] = nr[j];
        __syncwarp();

        // ---- phase 2: A = nr @ We1, B = nr @ We2, self = mish(A + B + b_edge) ----
        u64 aA0[8], aA1[8], aB0[8], aB1[8];
        u64 z = pack2(0.f, 0.f);
        #pragma unroll
        for (int j = 0; j < 8; j++) { aA0[j] = z; aA1[j] = z; aB0[j] = z; aB1[j] = z; }

        for (int k0 = 0; k0 < D; k0 += 4) {
            ulonglong2 p0 = __ldg((const ulonglong2*)(We + (size_t)(k0 + 0) * D + c));
            ulonglong2 p1 = __ldg((const ulonglong2*)(We + (size_t)(k0 + 1) * D + c));
            ulonglong2 p2 = __ldg((const ulonglong2*)(We + (size_t)(k0 + 2) * D + c));
            ulonglong2 p3 = __ldg((const ulonglong2*)(We + (size_t)(k0 + 3) * D + c));
            ulonglong2 q0 = __ldg((const ulonglong2*)(We + (size_t)(D + k0 + 0) * D + c));
            ulonglong2 q1 = __ldg((const ulonglong2*)(We + (size_t)(D + k0 + 1) * D + c));
            ulonglong2 q2 = __ldg((const ulonglong2*)(We + (size_t)(D + k0 + 2) * D + c));
            ulonglong2 q3 = __ldg((const ulonglong2*)(We + (size_t)(D + k0 + 3) * D + c));
            #pragma unroll
            for (int j = 0; j < 8; j++) {
                float4 a4 = *(const float4*)&xs[wy + 8 * j][k0];
                u64 aa;
                aa = pack2(a4.x, a4.x);
                aA0[j] = ffma2(aa, p0.x, aA0[j]); aA1[j] = ffma2(aa, p0.y, aA1[j]);
                aB0[j] = ffma2(aa, q0.x, aB0[j]); aB1[j] = ffma2(aa, q0.y, aB1[j]);
                aa = pack2(a4.y, a4.y);
                aA0[j] = ffma2(aa, p1.x, aA0[j]); aA1[j] = ffma2(aa, p1.y, aA1[j]);
                aB0[j] = ffma2(aa, q1.x, aB0[j]); aB1[j] = ffma2(aa, q1.y, aB1[j]);
                aa = pack2(a4.z, a4.z);
                aA0[j] = ffma2(aa, p2.x, aA0[j]); aA1[j] = ffma2(aa, p2.y, aA1[j]);
                aB0[j] = ffma2(aa, q2.x, aB0[j]); aB1[j] = ffma2(aa, q2.y, aB1[j]);
                aa = pack2(a4.w, a4.w);
                aA0[j] = ffma2(aa, p3.x, aA0[j]); aA1[j] = ffma2(aa, p3.y, aA1[j]);
                aB0[j] = ffma2(aa, q3.x, aB0[j]); aB1[j] = ffma2(aa, q3.y, aB1[j]);
            }
        }

        float4 be4 = __ldg((const float4*)&be[c]);
        #pragma unroll
        for (int j = 0; j < 8; j++) {
            size_t row = row0 + wy + 8 * j;
            float2 alo = unpack2(aA0[j]), ahi = unpack2(aA1[j]);
            float2 blo = unpack2(aB0[j]), bhi = unpack2(aB1[j]);
            float4 av = make_float4(alo.x, alo.y, ahi.x, ahi.y);
            float4 bv = make_float4(blo.x, blo.y, bhi.x, bhi.y);
            *(float4*)&g_A[row * D + c] = av;
            *(float4*)&g_B[row * D + c] = bv;
            float4 s = make_float4(av.x + bv.x + be4.x, av.y + bv.y + be4.y,
                                   av.z + bv.z + be4.z, av.w + bv.w + be4.w);
            *(float4*)&self_out[row * D + c] = mish4(s);
        }
        __syncwarp();
    }
}

// ---------------- kernel 4: edges = mean over pairs of mish(A[src] + B[dst] + b) ----------------
__global__ __launch_bounds__(256) void k_edge(
    const void* __restrict__ ei, const float* __restrict__ be,
    float* __restrict__ edge_out, int E)
{
    int is64 = d_is64[1];
    int lane = threadIdx.x & 31;
    int warp = blockIdx.x * (blockDim.x >> 5) + (threadIdx.x >> 5);
    int nwarps = gridDim.x * (blockDim.x >> 5);
    int c = lane * 4;
    float4 be4 = __ldg((const float4*)&be[c]);
    int pairs = E >> 1;
    for (int p = warp; p < pairs; p += nwarps) {
        long e0 = 2L * p;
        long s0 = ldx(ei, e0, is64);
        long s1 = ldx(ei, e0 + 1, is64);
        long d0 = ldx(ei, (long)E + e0, is64);
        long d1 = ldx(ei, (long)E + e0 + 1, is64);
        float4 a0 = __ldg((const float4*)&g_A[(size_t)s0 * D + c]);
        float4 b0 = __ldg((const float4*)&g_B[(size_t)d0 * D + c]);
        float4 a1 = __ldg((const float4*)&g_A[(size_t)s1 * D + c]);
        float4 b1 = __ldg((const float4*)&g_B[(size_t)d1 * D + c]);
        float4 v0 = mish4(make_float4(a0.x + b0.x + be4.x, a0.y + b0.y + be4.y,
                                      a0.z + b0.z + be4.z, a0.w + b0.w + be4.w));
        float4 v1 = mish4(make_float4(a1.x + b1.x + be4.x, a1.y + b1.y + be4.y,
                                      a1.z + b1.z + be4.z, a1.w + b1.w + be4.w));
        float4 o = make_float4(0.5f * (v0.x + v1.x), 0.5f * (v0.y + v1.y),
                               0.5f * (v0.z + v1.z), 0.5f * (v0.w + v1.w));
        *(float4*)&edge_out[(size_t)p * D + c] = o;
    }
}

// ---------------- launch ----------------
extern "C" void kernel_launch(void* const* d_in, const int* in_sizes, int n_in,
                              void* d_out, int out_size)
{
    const float* x     = (const float*)d_in[0];
    const void*  batch = d_in[1];
    const void*  ei    = d_in[2];
    const float* Wn    = (const float*)d_in[3];
    const float* bn    = (const float*)d_in[4];
    const float* We    = (const float*)d_in[5];
    const float* bee   = (const float*)d_in[6];
    const float* Wp    = (const float*)d_in[7];
    const float* bp    = (const float*)d_in[8];

    int N = in_sizes[0] / D;       // 524288 (derived from unambiguous float buffer)
    int E = MAXE;                  // fixed problem size

    float* out       = (float*)d_out;
    float* node_out  = out;
    float* self_out  = out + (size_t)N * D;
    float* edge_out  = out + 2 * (size_t)N * D;
    float* graph_out = out + 3 * (size_t)N * D;

    k_detect<<<1, 32>>>((const unsigned*)batch, N, (const unsigned*)ei);
    k_pool<<<NG, 128>>>(x, batch, N);
    k_graphmm<<<NG / 64, 256>>>(Wn, bn, Wp, bp, graph_out, NG);
    k_fuse<<<N / 64, 256>>>(x, batch, Wn, We, bee, node_out, self_out, N);
    k_edge<<<2048, 256>>>(ei, bee, edge_out, E);
}

// round 3
// speedup vs baseline: 1.1963x; 1.1963x over previous
#include <cuda_runtime.h>

#define D   128
#define NG  16384
#define MAXN 524288
#define MAXE 1048576

typedef unsigned long long u64;

// ---------------- device scratch (no allocations allowed) ----------------
__device__ int   d_is64[2];                      // [0]=batch is int64, [1]=edge_index is int64
__device__ float g_g  [(size_t)NG * D];          // pooled graph means  [G,128]
__device__ float g_gW2[(size_t)NG * D];          // b_node + g @ Wn2    [G,128]
__device__ float g_A  [(size_t)MAXN * D];        // node_rep @ We1      [N,128]
__device__ float g_B  [(size_t)MAXN * D];        // node_rep @ We2      [N,128]

// ---------------- helpers ----------------
__device__ __forceinline__ u64 pack2(float x, float y) {
    u64 r; asm("mov.b64 %0, {%1,%2};" : "=l"(r) : "f"(x), "f"(y)); return r;
}
__device__ __forceinline__ float2 unpack2(u64 v) {
    float2 f; asm("mov.b64 {%0,%1}, %2;" : "=f"(f.x), "=f"(f.y) : "l"(v)); return f;
}
// packed fp32 FMA (FFMA2) — sm_100+/sm_103a
__device__ __forceinline__ u64 ffma2(u64 a, u64 b, u64 c) {
    u64 d; asm("fma.rn.f32x2 %0, %1, %2, %3;" : "=l"(d) : "l"(a), "l"(b), "l"(c)); return d;
}

__device__ __forceinline__ long ldx(const void* p, long i, int is64) {
    if (is64) return (long)__ldg((const long long*)p + i);
    return (long)__ldg((const int*)p + i);
}

// mish(x) = x * tanh(softplus(x)) = x * ((1+e^x)^2 - 1) / ((1+e^x)^2 + 1)
__device__ __forceinline__ float mish1(float x) {
    float t = __expf(x);
    float u = t * t + 2.f * t;           // (1+t)^2 - 1
    float r = x * (u / (u + 2.f));
    return (x > 20.f) ? x : r;
}
__device__ __forceinline__ float4 mish4(float4 v) {
    v.x = mish1(v.x); v.y = mish1(v.y); v.z = mish1(v.z); v.w = mish1(v.w);
    return v;
}

// ---------------- kernel 0: dtype detection (int64 vs int32 indices) ----------------
__global__ void k_detect(const unsigned* __restrict__ b, int nb, const unsigned* __restrict__ e) {
    if (threadIdx.x == 0 && blockIdx.x == 0) {
        d_is64[0] = (b[nb - 1] == 0u && b[nb - 3] == 0u) ? 1 : 0;
        d_is64[1] = (e[1] == 0u && e[3] == 0u && e[5] == 0u && e[7] == 0u) ? 1 : 0;
    }
}

// ---------------- kernel 1: segment mean (batch is sorted -> binary search) ----------------
__global__ void k_pool(const float* __restrict__ x, const void* __restrict__ batch, int N) {
    int gid = blockIdx.x;          // one block per graph
    int t = threadIdx.x;           // 128 threads = one column each
    int is64 = d_is64[0];
    __shared__ int s_lo, s_hi;
    if (t == 0) {
        int lo = 0, hi = N;
        while (lo < hi) { int m = (lo + hi) >> 1; if (ldx(batch, m, is64) < (long)gid) lo = m + 1; else hi = m; }
        s_lo = lo;
        hi = N;
        while (lo < hi) { int m = (lo + hi) >> 1; if (ldx(batch, m, is64) < (long)gid + 1) lo = m + 1; else hi = m; }
        s_hi = lo;
    }
    __syncthreads();
    int lo = s_lo, hi = s_hi;
    float sum = 0.f;
    for (int i = lo; i < hi; i++) sum += __ldg(&x[(size_t)i * D + t]);
    float cnt = (float)(hi - lo);
    g_g[(size_t)gid * D + t] = sum / fmaxf(cnt, 1.f);
}

// ---------------- kernel 2: gW2 = b_node + g@Wn2 ; graph_rep = b_pool + g@W_pool ----------------
__global__ __launch_bounds__(256) void k_graphmm(
    const float* __restrict__ Wn, const float* __restrict__ bn,
    const float* __restrict__ Wp, const float* __restrict__ bp,
    float* __restrict__ graph_out, int G)
{
    __shared__ float gs[64][D];
    int lane = threadIdx.x & 31, wy = threadIdx.x >> 5;
    int c = lane * 4;

    for (int row0 = blockIdx.x * 64; row0 < G; row0 += gridDim.x * 64) {
        #pragma unroll
        for (int j = 0; j < 8; j++) {
            int r = wy + 8 * j;
            *(float4*)&gs[r][c] = *(const float4*)&g_g[(size_t)(row0 + r) * D + c];
        }
        __syncwarp();

        float4 acc2[8], accP[8];
        float4 bn4 = __ldg((const float4*)&bn[c]);
        float4 bp4 = __ldg((const float4*)&bp[c]);
        #pragma unroll
        for (int j = 0; j < 8; j++) { acc2[j] = bn4; accP[j] = bp4; }

        for (int k = 0; k < D; k++) {
            float4 w2 = __ldg((const float4*)&Wn[(size_t)(D + k) * D + c]);
            float4 wp = __ldg((const float4*)&Wp[(size_t)k * D + c]);
            #pragma unroll
            for (int j = 0; j < 8; j++) {
                float a = gs[wy + 8 * j][k];
                acc2[j].x = fmaf(a, w2.x, acc2[j].x); acc2[j].y = fmaf(a, w2.y, acc2[j].y);
                acc2[j].z = fmaf(a, w2.z, acc2[j].z); acc2[j].w = fmaf(a, w2.w, acc2[j].w);
                accP[j].x = fmaf(a, wp.x, accP[j].x); accP[j].y = fmaf(a, wp.y, accP[j].y);
                accP[j].z = fmaf(a, wp.z, accP[j].z); accP[j].w = fmaf(a, wp.w, accP[j].w);
            }
        }
        #pragma unroll
        for (int j = 0; j < 8; j++) {
            size_t row = row0 + wy + 8 * j;
            *(float4*)&g_gW2[row * D + c] = acc2[j];
            *(float4*)&graph_out[row * D + c] = accP[j];
        }
        __syncwarp();
    }
}

// ---------------- kernel 3: fused node MLP + A/B precompute + self-edge ----------------
// 64-row tile, 8 warps; warp wy owns rows {wy, wy+8, ..., wy+56}.
// x / nr tile stored in smem PRE-DUPLICATED as f32x2 pairs -> inner loop is
// pure LDS.128(broadcast) + FFMA2, zero pack instructions.
// Phase 2 split into two k-passes (A then B) to keep regs <= 128 for 2 CTAs/SM.
__global__ __launch_bounds__(256, 2) void k_fuse(
    const float* __restrict__ x, const void* __restrict__ batch,
    const float* __restrict__ Wn, const float* __restrict__ We,
    const float* __restrict__ be,
    float* __restrict__ node_out, float* __restrict__ self_out, int N)
{
    extern __shared__ u64 xs[];              // [64][128] duplicated pairs = 64 KB
    int lane = threadIdx.x & 31, wy = threadIdx.x >> 5;
    int c = lane * 4;
    int is64 = d_is64[0];

    for (int row0 = blockIdx.x * 64; row0 < N; row0 += gridDim.x * 64) {
        // ---- load & duplicate x tile (each warp its own rows) ----
        #pragma unroll
        for (int j = 0; j < 8; j++) {
            int r = wy + 8 * j;
            float4 v = __ldg((const float4*)&x[(size_t)(row0 + r) * D + c]);
            ulonglong2 lo, hi;
            lo.x = pack2(v.x, v.x); lo.y = pack2(v.y, v.y);
            hi.x = pack2(v.z, v.z); hi.y = pack2(v.w, v.w);
            *(ulonglong2*)&xs[(size_t)r * D + c]     = lo;
            *(ulonglong2*)&xs[(size_t)r * D + c + 2] = hi;
        }
        __syncwarp();

        // ---- phase 1: nr = mish(x @ Wn1 + gW2[batch]) ----
        u64 acc0[8], acc1[8];
        #pragma unroll
        for (int j = 0; j < 8; j++) {
            long r = row0 + wy + 8 * j;
            long b = ldx(batch, r, is64);
            ulonglong2 gv = __ldg((const ulonglong2*)(g_gW2 + (size_t)b * D + c));
            acc0[j] = gv.x; acc1[j] = gv.y;
        }
        #pragma unroll 2
        for (int k0 = 0; k0 < D; k0 += 4) {
            ulonglong2 w0 = __ldg((const ulonglong2*)(Wn + (size_t)(k0 + 0) * D + c));
            ulonglong2 w1 = __ldg((const ulonglong2*)(Wn + (size_t)(k0 + 1) * D + c));
            ulonglong2 w2 = __ldg((const ulonglong2*)(Wn + (size_t)(k0 + 2) * D + c));
            ulonglong2 w3 = __ldg((const ulonglong2*)(Wn + (size_t)(k0 + 3) * D + c));
            #pragma unroll
            for (int j = 0; j < 8; j++) {
                const u64* xr = &xs[(size_t)(wy + 8 * j) * D + k0];
                ulonglong2 aX = *(const ulonglong2*)xr;
                ulonglong2 aY = *(const ulonglong2*)(xr + 2);
                acc0[j] = ffma2(aX.x, w0.x, acc0[j]); acc1[j] = ffma2(aX.x, w0.y, acc1[j]);
                acc0[j] = ffma2(aX.y, w1.x, acc0[j]); acc1[j] = ffma2(aX.y, w1.y, acc1[j]);
                acc0[j] = ffma2(aY.x, w2.x, acc0[j]); acc1[j] = ffma2(aY.x, w2.y, acc1[j]);
                acc0[j] = ffma2(aY.y, w3.x, acc0[j]); acc1[j] = ffma2(aY.y, w3.y, acc1[j]);
            }
        }
        #pragma unroll
        for (int j = 0; j < 8; j++) {
            int r = wy + 8 * j;
            float2 lo = unpack2(acc0[j]), hi = unpack2(acc1[j]);
            float4 v = make_float4(mish1(lo.x), mish1(lo.y), mish1(hi.x), mish1(hi.y));
            *(float4*)&node_out[((size_t)row0 + r) * D + c] = v;
            ulonglong2 dl, dh;
            dl.x = pack2(v.x, v.x); dl.y = pack2(v.y, v.y);
            dh.x = pack2(v.z, v.z); dh.y = pack2(v.w, v.w);
            *(ulonglong2*)&xs[(size_t)r * D + c]     = dl;
            *(ulonglong2*)&xs[(size_t)r * D + c + 2] = dh;
        }
        __syncwarp();

        // ---- pass A: aA = nr @ We1, write g_A (aA stays live for self-edge) ----
        u64 aA0[8], aA1[8];
        u64 z = pack2(0.f, 0.f);
        #pragma unroll
        for (int j = 0; j < 8; j++) { aA0[j] = z; aA1[j] = z; }
        #pragma unroll 2
        for (int k0 = 0; k0 < D; k0 += 4) {
            ulonglong2 p0 = __ldg((const ulonglong2*)(We + (size_t)(k0 + 0) * D + c));
            ulonglong2 p1 = __ldg((const ulonglong2*)(We + (size_t)(k0 + 1) * D + c));
            ulonglong2 p2 = __ldg((const ulonglong2*)(We + (size_t)(k0 + 2) * D + c));
            ulonglong2 p3 = __ldg((const ulonglong2*)(We + (size_t)(k0 + 3) * D + c));
            #pragma unroll
            for (int j = 0; j < 8; j++) {
                const u64* xr = &xs[(size_t)(wy + 8 * j) * D + k0];
                ulonglong2 aX = *(const ulonglong2*)xr;
                ulonglong2 aY = *(const ulonglong2*)(xr + 2);
                aA0[j] = ffma2(aX.x, p0.x, aA0[j]); aA1[j] = ffma2(aX.x, p0.y, aA1[j]);
                aA0[j] = ffma2(aX.y, p1.x, aA0[j]); aA1[j] = ffma2(aX.y, p1.y, aA1[j]);
                aA0[j] = ffma2(aY.x, p2.x, aA0[j]); aA1[j] = ffma2(aY.x, p2.y, aA1[j]);
                aA0[j] = ffma2(aY.y, p3.x, aA0[j]); aA1[j] = ffma2(aY.y, p3.y, aA1[j]);
            }
        }
        #pragma unroll
        for (int j = 0; j < 8; j++) {
            size_t row = row0 + wy + 8 * j;
            float2 lo = unpack2(aA0[j]), hi = unpack2(aA1[j]);
            *(float4*)&g_A[row * D + c] = make_float4(lo.x, lo.y, hi.x, hi.y);
        }

        // ---- pass B: aB = nr @ We2, write g_B, self = mish(aA + aB + be) ----
        u64 aB0[8], aB1[8];
        #pragma unroll
        for (int j = 0; j < 8; j++) { aB0[j] = z; aB1[j] = z; }
        #pragma unroll 2
        for (int k0 = 0; k0 < D; k0 += 4) {
            ulonglong2 q0 = __ldg((const ulonglong2*)(We + (size_t)(D + k0 + 0) * D + c));
            ulonglong2 q1 = __ldg((const ulonglong2*)(We + (size_t)(D + k0 + 1) * D + c));
            ulonglong2 q2 = __ldg((const ulonglong2*)(We + (size_t)(D + k0 + 2) * D + c));
            ulonglong2 q3 = __ldg((const ulonglong2*)(We + (size_t)(D + k0 + 3) * D + c));
            #pragma unroll
            for (int j = 0; j < 8; j++) {
                const u64* xr = &xs[(size_t)(wy + 8 * j) * D + k0];
                ulonglong2 aX = *(const ulonglong2*)xr;
                ulonglong2 aY = *(const ulonglong2*)(xr + 2);
                aB0[j] = ffma2(aX.x, q0.x, aB0[j]); aB1[j] = ffma2(aX.x, q0.y, aB1[j]);
                aB0[j] = ffma2(aX.y, q1.x, aB0[j]); aB1[j] = ffma2(aX.y, q1.y, aB1[j]);
                aB0[j] = ffma2(aY.x, q2.x, aB0[j]); aB1[j] = ffma2(aY.x, q2.y, aB1[j]);
                aB0[j] = ffma2(aY.y, q3.x, aB0[j]); aB1[j] = ffma2(aY.y, q3.y, aB1[j]);
            }
        }
        float4 be4 = __ldg((const float4*)&be[c]);
        #pragma unroll
        for (int j = 0; j < 8; j++) {
            size_t row = row0 + wy + 8 * j;
            float2 blo = unpack2(aB0[j]), bhi = unpack2(aB1[j]);
            float4 bv = make_float4(blo.x, blo.y, bhi.x, bhi.y);
            *(float4*)&g_B[row * D + c] = bv;
            float2 alo = unpack2(aA0[j]), ahi = unpack2(aA1[j]);
            float4 s = make_float4(alo.x + bv.x + be4.x, alo.y + bv.y + be4.y,
                                   ahi.x + bv.z + be4.z, ahi.y + bv.w + be4.w);
            *(float4*)&self_out[row * D + c] = mish4(s);
        }
        __syncwarp();
    }
}

// ---------------- kernel 4: edges = mean over pairs of mish(A[src] + B[dst] + b) ----------------
__global__ __launch_bounds__(256) void k_edge(
    const void* __restrict__ ei, const float* __restrict__ be,
    float* __restrict__ edge_out, int E)
{
    int is64 = d_is64[1];
    int lane = threadIdx.x & 31;
    int warp = blockIdx.x * (blockDim.x >> 5) + (threadIdx.x >> 5);
    int nwarps = gridDim.x * (blockDim.x >> 5);
    int c = lane * 4;
    float4 be4 = __ldg((const float4*)&be[c]);
    int pairs = E >> 1;
    for (int p = warp; p < pairs; p += nwarps) {
        long e0 = 2L * p;
        long s0 = ldx(ei, e0, is64);
        long s1 = ldx(ei, e0 + 1, is64);
        long d0 = ldx(ei, (long)E + e0, is64);
        long d1 = ldx(ei, (long)E + e0 + 1, is64);
        float4 a0 = __ldg((const float4*)&g_A[(size_t)s0 * D + c]);
        float4 b0 = __ldg((const float4*)&g_B[(size_t)d0 * D + c]);
        float4 a1 = __ldg((const float4*)&g_A[(size_t)s1 * D + c]);
        float4 b1 = __ldg((const float4*)&g_B[(size_t)d1 * D + c]);
        float4 v0 = mish4(make_float4(a0.x + b0.x + be4.x, a0.y + b0.y + be4.y,
                                      a0.z + b0.z + be4.z, a0.w + b0.w + be4.w));
        float4 v1 = mish4(make_float4(a1.x + b1.x + be4.x, a1.y + b1.y + be4.y,
                                      a1.z + b1.z + be4.z, a1.w + b1.w + be4.w));
        float4 o = make_float4(0.5f * (v0.x + v1.x), 0.5f * (v0.y + v1.y),
                               0.5f * (v0.z + v1.z), 0.5f * (v0.w + v1.w));
        *(float4*)&edge_out[(size_t)p * D + c] = o;
    }
}

// ---------------- launch ----------------
extern "C" void kernel_launch(void* const* d_in, const int* in_sizes, int n_in,
                              void* d_out, int out_size)
{
    const float* x     = (const float*)d_in[0];
    const void*  batch = d_in[1];
    const void*  ei    = d_in[2];
    const float* Wn    = (const float*)d_in[3];
    const float* bn    = (const float*)d_in[4];
    const float* We    = (const float*)d_in[5];
    const float* bee   = (const float*)d_in[6];
    const float* Wp    = (const float*)d_in[7];
    const float* bp    = (const float*)d_in[8];

    int N = in_sizes[0] / D;       // 524288
    int E = MAXE;

    float* out       = (float*)d_out;
    float* node_out  = out;
    float* self_out  = out + (size_t)N * D;
    float* edge_out  = out + 2 * (size_t)N * D;
    float* graph_out = out + 3 * (size_t)N * D;

    static int smem_set = 0;
    if (!smem_set) {
        cudaFuncSetAttribute(k_fuse, cudaFuncAttributeMaxDynamicSharedMemorySize, 65536);
        smem_set = 1;
    }

    k_detect<<<1, 32>>>((const unsigned*)batch, N, (const unsigned*)ei);
    k_pool<<<NG, 128>>>(x, batch, N);
    k_graphmm<<<NG / 64, 256>>>(Wn, bn, Wp, bp, graph_out, NG);
    k_fuse<<<N / 64, 256, 65536>>>(x, batch, Wn, We, bee, node_out, self_out, N);
    k_edge<<<2048, 256>>>(ei, bee, edge_out, E);
}

// round 4
// speedup vs baseline: 1.3478x; 1.1266x over previous
#include <cuda_runtime.h>

#define D   128
#define NG  16384
#define MAXN 524288
#define MAXE 1048576

typedef unsigned long long u64;

// ---------------- device scratch (no allocations allowed) ----------------
__device__ int   d_is64[2];                      // [0]=batch is int64, [1]=edge_index is int64
__device__ float g_g  [(size_t)NG * D];          // pooled graph means  [G,128]
__device__ float g_gW2[(size_t)NG * D];          // b_node + g @ Wn2    [G,128]
__device__ float g_A  [(size_t)MAXN * D];        // node_rep @ We1      [N,128]
__device__ float g_B  [(size_t)MAXN * D];        // node_rep @ We2      [N,128]

// ---------------- helpers ----------------
__device__ __forceinline__ u64 pack2(float x, float y) {
    u64 r; asm("mov.b64 %0, {%1,%2};" : "=l"(r) : "f"(x), "f"(y)); return r;
}
__device__ __forceinline__ float2 unpack2(u64 v) {
    float2 f; asm("mov.b64 {%0,%1}, %2;" : "=f"(f.x), "=f"(f.y) : "l"(v)); return f;
}
// packed fp32 FMA (FFMA2) — sm_100+/sm_103a
__device__ __forceinline__ u64 ffma2(u64 a, u64 b, u64 c) {
    u64 d; asm("fma.rn.f32x2 %0, %1, %2, %3;" : "=l"(d) : "l"(a), "l"(b), "l"(c)); return d;
}

__device__ __forceinline__ long ldx(const void* p, long i, int is64) {
    if (is64) return (long)__ldg((const long long*)p + i);
    return (long)__ldg((const int*)p + i);
}

// mish(x) = x * tanh(softplus(x)) = x * ((1+e^x)^2 - 1) / ((1+e^x)^2 + 1)
__device__ __forceinline__ float mish1(float x) {
    float t = __expf(x);
    float u = t * t + 2.f * t;           // (1+t)^2 - 1
    float r = x * (u / (u + 2.f));
    return (x > 20.f) ? x : r;
}
__device__ __forceinline__ float4 mish4(float4 v) {
    v.x = mish1(v.x); v.y = mish1(v.y); v.z = mish1(v.z); v.w = mish1(v.w);
    return v;
}

// ---------------- kernel 0: dtype detection (int64 vs int32 indices) ----------------
__global__ void k_detect(const unsigned* __restrict__ b, int nb, const unsigned* __restrict__ e) {
    if (threadIdx.x == 0 && blockIdx.x == 0) {
        d_is64[0] = (b[nb - 1] == 0u && b[nb - 3] == 0u) ? 1 : 0;
        d_is64[1] = (e[1] == 0u && e[3] == 0u && e[5] == 0u && e[7] == 0u) ? 1 : 0;
    }
}

// ---------------- kernel 1: segment mean (batch is sorted -> binary search) ----------------
__global__ void k_pool(const float* __restrict__ x, const void* __restrict__ batch, int N) {
    int gid = blockIdx.x;          // one block per graph
    int t = threadIdx.x;           // 128 threads = one column each
    int is64 = d_is64[0];
    __shared__ int s_lo, s_hi;
    if (t == 0) {
        int lo = 0, hi = N;
        while (lo < hi) { int m = (lo + hi) >> 1; if (ldx(batch, m, is64) < (long)gid) lo = m + 1; else hi = m; }
        s_lo = lo;
        hi = N;
        while (lo < hi) { int m = (lo + hi) >> 1; if (ldx(batch, m, is64) < (long)gid + 1) lo = m + 1; else hi = m; }
        s_hi = lo;
    }
    __syncthreads();
    int lo = s_lo, hi = s_hi;
    float sum = 0.f;
    for (int i = lo; i < hi; i++) sum += __ldg(&x[(size_t)i * D + t]);
    float cnt = (float)(hi - lo);
    g_g[(size_t)gid * D + t] = sum / fmaxf(cnt, 1.f);
}

// ---------------- kernel 2: gW2 = b_node + g@Wn2 ; graph_rep = b_pool + g@W_pool ----------------
__global__ __launch_bounds__(256) void k_graphmm(
    const float* __restrict__ Wn, const float* __restrict__ bn,
    const float* __restrict__ Wp, const float* __restrict__ bp,
    float* __restrict__ graph_out, int G)
{
    __shared__ float gs[64][D];
    int lane = threadIdx.x & 31, wy = threadIdx.x >> 5;
    int c = lane * 4;

    for (int row0 = blockIdx.x * 64; row0 < G; row0 += gridDim.x * 64) {
        #pragma unroll
        for (int j = 0; j < 8; j++) {
            int r = wy + 8 * j;
            *(float4*)&gs[r][c] = *(const float4*)&g_g[(size_t)(row0 + r) * D + c];
        }
        __syncwarp();

        float4 acc2[8], accP[8];
        float4 bn4 = __ldg((const float4*)&bn[c]);
        float4 bp4 = __ldg((const float4*)&bp[c]);
        #pragma unroll
        for (int j = 0; j < 8; j++) { acc2[j] = bn4; accP[j] = bp4; }

        for (int k = 0; k < D; k++) {
            float4 w2 = __ldg((const float4*)&Wn[(size_t)(D + k) * D + c]);
            float4 wp = __ldg((const float4*)&Wp[(size_t)k * D + c]);
            #pragma unroll
            for (int j = 0; j < 8; j++) {
                float a = gs[wy + 8 * j][k];
                acc2[j].x = fmaf(a, w2.x, acc2[j].x); acc2[j].y = fmaf(a, w2.y, acc2[j].y);
                acc2[j].z = fmaf(a, w2.z, acc2[j].z); acc2[j].w = fmaf(a, w2.w, acc2[j].w);
                accP[j].x = fmaf(a, wp.x, accP[j].x); accP[j].y = fmaf(a, wp.y, accP[j].y);
                accP[j].z = fmaf(a, wp.z, accP[j].z); accP[j].w = fmaf(a, wp.w, accP[j].w);
            }
        }
        #pragma unroll
        for (int j = 0; j < 8; j++) {
            size_t row = row0 + wy + 8 * j;
            *(float4*)&g_gW2[row * D + c] = acc2[j];
            *(float4*)&graph_out[row * D + c] = accP[j];
        }
        __syncwarp();
    }
}

// ---------------- kernel 3: fused node MLP + A/B precompute + self-edge ----------------
// 64-row tile, 8 warps; warp wy owns rows {wy, wy+8, ..., wy+56}.
// Plain-float smem tile (broadcast LDS.128) + pack2 in registers: per warp-k0
// block: 8 LDS.128 + 4 LDG.128 + 32 pack (alu) + 64 FFMA2. Split A/B passes
// keep regs <= 128 for 2 CTAs/SM.
__global__ __launch_bounds__(256, 2) void k_fuse(
    const float* __restrict__ x, const void* __restrict__ batch,
    const float* __restrict__ Wn, const float* __restrict__ We,
    const float* __restrict__ be,
    float* __restrict__ node_out, float* __restrict__ self_out, int N)
{
    __shared__ float xs[64][D];
    int lane = threadIdx.x & 31, wy = threadIdx.x >> 5;
    int c = lane * 4;
    int is64 = d_is64[0];

    for (int row0 = blockIdx.x * 64; row0 < N; row0 += gridDim.x * 64) {
        // ---- load x tile (each warp its own rows) ----
        #pragma unroll
        for (int j = 0; j < 8; j++) {
            int r = wy + 8 * j;
            *(float4*)&xs[r][c] = __ldg((const float4*)&x[(size_t)(row0 + r) * D + c]);
        }
        __syncwarp();

        // ---- phase 1: nr = mish(x @ Wn1 + gW2[batch]) ----
        u64 acc0[8], acc1[8];
        #pragma unroll
        for (int j = 0; j < 8; j++) {
            long r = row0 + wy + 8 * j;
            long b = ldx(batch, r, is64);
            ulonglong2 gv = __ldg((const ulonglong2*)(g_gW2 + (size_t)b * D + c));
            acc0[j] = gv.x; acc1[j] = gv.y;
        }
        #pragma unroll 2
        for (int k0 = 0; k0 < D; k0 += 4) {
            ulonglong2 w0 = __ldg((const ulonglong2*)(Wn + (size_t)(k0 + 0) * D + c));
            ulonglong2 w1 = __ldg((const ulonglong2*)(Wn + (size_t)(k0 + 1) * D + c));
            ulonglong2 w2 = __ldg((const ulonglong2*)(Wn + (size_t)(k0 + 2) * D + c));
            ulonglong2 w3 = __ldg((const ulonglong2*)(Wn + (size_t)(k0 + 3) * D + c));
            #pragma unroll
            for (int j = 0; j < 8; j++) {
                float4 a4 = *(const float4*)&xs[wy + 8 * j][k0];
                u64 aa;
                aa = pack2(a4.x, a4.x); acc0[j] = ffma2(aa, w0.x, acc0[j]); acc1[j] = ffma2(aa, w0.y, acc1[j]);
                aa = pack2(a4.y, a4.y); acc0[j] = ffma2(aa, w1.x, acc0[j]); acc1[j] = ffma2(aa, w1.y, acc1[j]);
                aa = pack2(a4.z, a4.z); acc0[j] = ffma2(aa, w2.x, acc0[j]); acc1[j] = ffma2(aa, w2.y, acc1[j]);
                aa = pack2(a4.w, a4.w); acc0[j] = ffma2(aa, w3.x, acc0[j]); acc1[j] = ffma2(aa, w3.y, acc1[j]);
            }
        }
        #pragma unroll
        for (int j = 0; j < 8; j++) {
            int r = wy + 8 * j;
            float2 lo = unpack2(acc0[j]), hi = unpack2(acc1[j]);
            float4 v = make_float4(mish1(lo.x), mish1(lo.y), mish1(hi.x), mish1(hi.y));
            *(float4*)&node_out[((size_t)row0 + r) * D + c] = v;
            *(float4*)&xs[r][c] = v;
        }
        __syncwarp();

        // ---- pass A: aA = nr @ We1, write g_A (aA stays live for self-edge) ----
        u64 aA0[8], aA1[8];
        u64 z = pack2(0.f, 0.f);
        #pragma unroll
        for (int j = 0; j < 8; j++) { aA0[j] = z; aA1[j] = z; }
        #pragma unroll 2
        for (int k0 = 0; k0 < D; k0 += 4) {
            ulonglong2 p0 = __ldg((const ulonglong2*)(We + (size_t)(k0 + 0) * D + c));
            ulonglong2 p1 = __ldg((const ulonglong2*)(We + (size_t)(k0 + 1) * D + c));
            ulonglong2 p2 = __ldg((const ulonglong2*)(We + (size_t)(k0 + 2) * D + c));
            ulonglong2 p3 = __ldg((const ulonglong2*)(We + (size_t)(k0 + 3) * D + c));
            #pragma unroll
            for (int j = 0; j < 8; j++) {
                float4 a4 = *(const float4*)&xs[wy + 8 * j][k0];
                u64 aa;
                aa = pack2(a4.x, a4.x); aA0[j] = ffma2(aa, p0.x, aA0[j]); aA1[j] = ffma2(aa, p0.y, aA1[j]);
                aa = pack2(a4.y, a4.y); aA0[j] = ffma2(aa, p1.x, aA0[j]); aA1[j] = ffma2(aa, p1.y, aA1[j]);
                aa = pack2(a4.z, a4.z); aA0[j] = ffma2(aa, p2.x, aA0[j]); aA1[j] = ffma2(aa, p2.y, aA1[j]);
                aa = pack2(a4.w, a4.w); aA0[j] = ffma2(aa, p3.x, aA0[j]); aA1[j] = ffma2(aa, p3.y, aA1[j]);
            }
        }
        #pragma unroll
        for (int j = 0; j < 8; j++) {
            size_t row = row0 + wy + 8 * j;
            float2 lo = unpack2(aA0[j]), hi = unpack2(aA1[j]);
            *(float4*)&g_A[row * D + c] = make_float4(lo.x, lo.y, hi.x, hi.y);
        }

        // ---- pass B: aB = nr @ We2, write g_B, self = mish(aA + aB + be) ----
        u64 aB0[8], aB1[8];
        #pragma unroll
        for (int j = 0; j < 8; j++) { aB0[j] = z; aB1[j] = z; }
        #pragma unroll 2
        for (int k0 = 0; k0 < D; k0 += 4) {
            ulonglong2 q0 = __ldg((const ulonglong2*)(We + (size_t)(D + k0 + 0) * D + c));
            ulonglong2 q1 = __ldg((const ulonglong2*)(We + (size_t)(D + k0 + 1) * D + c));
            ulonglong2 q2 = __ldg((const ulonglong2*)(We + (size_t)(D + k0 + 2) * D + c));
            ulonglong2 q3 = __ldg((const ulonglong2*)(We + (size_t)(D + k0 + 3) * D + c));
            #pragma unroll
            for (int j = 0; j < 8; j++) {
                float4 a4 = *(const float4*)&xs[wy + 8 * j][k0];
                u64 aa;
                aa = pack2(a4.x, a4.x); aB0[j] = ffma2(aa, q0.x, aB0[j]); aB1[j] = ffma2(aa, q0.y, aB1[j]);
                aa = pack2(a4.y, a4.y); aB0[j] = ffma2(aa, q1.x, aB0[j]); aB1[j] = ffma2(aa, q1.y, aB1[j]);
                aa = pack2(a4.z, a4.z); aB0[j] = ffma2(aa, q2.x, aB0[j]); aB1[j] = ffma2(aa, q2.y, aB1[j]);
                aa = pack2(a4.w, a4.w); aB0[j] = ffma2(aa, q3.x, aB0[j]); aB1[j] = ffma2(aa, q3.y, aB1[j]);
            }
        }
        float4 be4 = __ldg((const float4*)&be[c]);
        #pragma unroll
        for (int j = 0; j < 8; j++) {
            size_t row = row0 + wy + 8 * j;
            float2 blo = unpack2(aB0[j]), bhi = unpack2(aB1[j]);
            float4 bv = make_float4(blo.x, blo.y, bhi.x, bhi.y);
            *(float4*)&g_B[row * D + c] = bv;
            float2 alo = unpack2(aA0[j]), ahi = unpack2(aA1[j]);
            float4 s = make_float4(alo.x + bv.x + be4.x, alo.y + bv.y + be4.y,
                                   ahi.x + bv.z + be4.z, ahi.y + bv.w + be4.w);
            *(float4*)&self_out[row * D + c] = mish4(s);
        }
        __syncwarp();
    }
}

// ---------------- kernel 4: edges = mean over pairs of mish(A[src] + B[dst] + b) ----------------
__global__ __launch_bounds__(256) void k_edge(
    const void* __restrict__ ei, const float* __restrict__ be,
    float* __restrict__ edge_out, int E)
{
    int is64 = d_is64[1];
    int lane = threadIdx.x & 31;
    int warp = blockIdx.x * (blockDim.x >> 5) + (threadIdx.x >> 5);
    int nwarps = gridDim.x * (blockDim.x >> 5);
    int c = lane * 4;
    float4 be4 = __ldg((const float4*)&be[c]);
    int pairs = E >> 1;
    for (int p = warp; p < pairs; p += nwarps) {
        long e0 = 2L * p;
        long s0 = ldx(ei, e0, is64);
        long s1 = ldx(ei, e0 + 1, is64);
        long d0 = ldx(ei, (long)E + e0, is64);
        long d1 = ldx(ei, (long)E + e0 + 1, is64);
        float4 a0 = __ldg((const float4*)&g_A[(size_t)s0 * D + c]);
        float4 b0 = __ldg((const float4*)&g_B[(size_t)d0 * D + c]);
        float4 a1 = __ldg((const float4*)&g_A[(size_t)s1 * D + c]);
        float4 b1 = __ldg((const float4*)&g_B[(size_t)d1 * D + c]);
        float4 v0 = mish4(make_float4(a0.x + b0.x + be4.x, a0.y + b0.y + be4.y,
                                      a0.z + b0.z + be4.z, a0.w + b0.w + be4.w));
        float4 v1 = mish4(make_float4(a1.x + b1.x + be4.x, a1.y + b1.y + be4.y,
                                      a1.z + b1.z + be4.z, a1.w + b1.w + be4.w));
        float4 o = make_float4(0.5f * (v0.x + v1.x), 0.5f * (v0.y + v1.y),
                               0.5f * (v0.z + v1.z), 0.5f * (v0.w + v1.w));
        *(float4*)&edge_out[(size_t)p * D + c] = o;
    }
}

// ---------------- launch ----------------
extern "C" void kernel_launch(void* const* d_in, const int* in_sizes, int n_in,
                              void* d_out, int out_size)
{
    const float* x     = (const float*)d_in[0];
    const void*  batch = d_in[1];
    const void*  ei    = d_in[2];
    const float* Wn    = (const float*)d_in[3];
    const float* bn    = (const float*)d_in[4];
    const float* We    = (const float*)d_in[5];
    const float* bee   = (const float*)d_in[6];
    const float* Wp    = (const float*)d_in[7];
    const float* bp    = (const float*)d_in[8];

    int N = in_sizes[0] / D;       // 524288
    int E = MAXE;

    float* out       = (float*)d_out;
    float* node_out  = out;
    float* self_out  = out + (size_t)N * D;
    float* edge_out  = out + 2 * (size_t)N * D;
    float* graph_out = out + 3 * (size_t)N * D;

    k_detect<<<1, 32>>>((const unsigned*)batch, N, (const unsigned*)ei);
    k_pool<<<NG, 128>>>(x, batch, N);
    k_graphmm<<<NG / 64, 256>>>(Wn, bn, Wp, bp, graph_out, NG);
    k_fuse<<<N / 64, 256>>>(x, batch, Wn, We, bee, node_out, self_out, N);
    k_edge<<<2048, 256>>>(ei, bee, edge_out, E);
}

// round 9
// speedup vs baseline: 1.8519x; 1.3740x over previous
#include <cuda_runtime.h>
#include <cuda_bf16.h>

#define D    128
#define NG   16384
#define MAXN 524288
#define MAXE 1048576
#define STRB 272              // smem row stride bytes (136 bf16) — conflict-free ldmatrix

typedef unsigned long long u64;

// ---------------- device scratch ----------------
__device__ int   d_is64[2];
__device__ float g_g  [(size_t)NG * D];
__device__ float g_gW2[(size_t)NG * D];
__device__ float g_A  [(size_t)MAXN * D];
__device__ float g_B  [(size_t)MAXN * D];

// ---------------- generic helpers ----------------
__device__ __forceinline__ long ldx(const void* p, long i, int is64) {
    if (is64) return (long)__ldg((const long long*)p + i);
    return (long)__ldg((const int*)p + i);
}
__device__ __forceinline__ float mish1(float x) {
    float t = __expf(x);
    float u = t * t + 2.f * t;
    float r = x * (u / (u + 2.f));
    return (x > 20.f) ? x : r;
}
__device__ __forceinline__ float4 mish4(float4 v) {
    v.x = mish1(v.x); v.y = mish1(v.y); v.z = mish1(v.z); v.w = mish1(v.w);
    return v;
}
__device__ __forceinline__ unsigned smem_u32(const void* p) {
    unsigned a; asm("{ .reg .u64 t; cvta.to.shared.u64 t, %1; cvt.u32.u64 %0, t; }" : "=r"(a) : "l"(p));
    return a;
}

// ---------------- warp MMA helpers (base ISA: sm_80+, OK for compute_103) ----------------
__device__ __forceinline__ void ldsm4(unsigned* r, unsigned addr) {
    asm volatile("ldmatrix.sync.aligned.m8n8.x4.shared.b16 {%0,%1,%2,%3}, [%4];"
        : "=r"(r[0]), "=r"(r[1]), "=r"(r[2]), "=r"(r[3]) : "r"(addr));
}
__device__ __forceinline__ void mma_bf16(float* c, const unsigned* a, unsigned b0, unsigned b1) {
    asm volatile("mma.sync.aligned.m16n8k16.row.col.f32.bf16.bf16.f32 "
        "{%0,%1,%2,%3}, {%4,%5,%6,%7}, {%8,%9}, {%0,%1,%2,%3};"
        : "+f"(c[0]), "+f"(c[1]), "+f"(c[2]), "+f"(c[3])
        : "r"(a[0]), "r"(a[1]), "r"(a[2]), "r"(a[3]), "r"(b0), "r"(b1));
}
// fp32x4 -> bf16 hi/lo packed pairs
__device__ __forceinline__ void split4(float4 v, uint2& H, uint2& L) {
    __nv_bfloat16 h0 = __float2bfloat16_rn(v.x), h1 = __float2bfloat16_rn(v.y);
    __nv_bfloat16 h2 = __float2bfloat16_rn(v.z), h3 = __float2bfloat16_rn(v.w);
    __nv_bfloat16 l0 = __float2bfloat16_rn(v.x - __bfloat162float(h0));
    __nv_bfloat16 l1 = __float2bfloat16_rn(v.y - __bfloat162float(h1));
    __nv_bfloat16 l2 = __float2bfloat16_rn(v.z - __bfloat162float(h2));
    __nv_bfloat16 l3 = __float2bfloat16_rn(v.w - __bfloat162float(h3));
    __nv_bfloat162 H01 = __halves2bfloat162(h0, h1), H23 = __halves2bfloat162(h2, h3);
    __nv_bfloat162 L01 = __halves2bfloat162(l0, l1), L23 = __halves2bfloat162(l2, l3);
    H = make_uint2(*(unsigned*)&H01, *(unsigned*)&H23);
    L = make_uint2(*(unsigned*)&L01, *(unsigned*)&L23);
}

// convert [128,128] fp32 W (row-major [k][n]) into TRANSPOSED bf16 smem [n][k] hi/lo
__device__ void conv_w(const float* __restrict__ W, char* sm, int off_h, int off_l) {
    for (int i = threadIdx.x; i < 128 * 32; i += blockDim.x) {
        int k = i >> 5, n4 = (i & 31) << 2;
        float4 v = __ldg((const float4*)&W[k * 128 + n4]);
        float vals[4] = {v.x, v.y, v.z, v.w};
        #pragma unroll
        for (int j = 0; j < 4; j++) {
            int n = n4 + j;
            __nv_bfloat16 h = __float2bfloat16_rn(vals[j]);
            __nv_bfloat16 l = __float2bfloat16_rn(vals[j] - __bfloat162float(h));
            *(__nv_bfloat16*)(sm + off_h + n * STRB + k * 2) = h;
            *(__nv_bfloat16*)(sm + off_l + n * STRB + k * 2) = l;
        }
    }
}

// ---------------- kernel 0: dtype detection ----------------
__global__ void k_detect(const unsigned* __restrict__ b, int nb, const unsigned* __restrict__ e) {
    if (threadIdx.x == 0 && blockIdx.x == 0) {
        d_is64[0] = (b[nb - 1] == 0u && b[nb - 3] == 0u) ? 1 : 0;
        d_is64[1] = (e[1] == 0u && e[3] == 0u && e[5] == 0u && e[7] == 0u) ? 1 : 0;
    }
}

// ---------------- kernel 1: segment mean ----------------
__global__ void k_pool(const float* __restrict__ x, const void* __restrict__ batch, int N) {
    int gid = blockIdx.x;
    int t = threadIdx.x;
    int is64 = d_is64[0];
    __shared__ int s_lo, s_hi;
    if (t == 0) {
        int lo = 0, hi = N;
        while (lo < hi) { int m = (lo + hi) >> 1; if (ldx(batch, m, is64) < (long)gid) lo = m + 1; else hi = m; }
        s_lo = lo;
        hi = N;
        while (lo < hi) { int m = (lo + hi) >> 1; if (ldx(batch, m, is64) < (long)gid + 1) lo = m + 1; else hi = m; }
        s_hi = lo;
    }
    __syncthreads();
    int lo = s_lo, hi = s_hi;
    float sum = 0.f;
    for (int i = lo; i < hi; i++) sum += __ldg(&x[(size_t)i * D + t]);
    float cnt = (float)(hi - lo);
    g_g[(size_t)gid * D + t] = sum / fmaxf(cnt, 1.f);
}

// ---------------- kernel 2: gW2 = b_node + g@Wn2 ; graph_rep = b_pool + g@W_pool ----------------
__global__ __launch_bounds__(256) void k_graphmm(
    const float* __restrict__ Wn, const float* __restrict__ bn,
    const float* __restrict__ Wp, const float* __restrict__ bp,
    float* __restrict__ graph_out, int G)
{
    __shared__ float gs[64][D];
    int lane = threadIdx.x & 31, wy = threadIdx.x >> 5;
    int c = lane * 4;
    for (int row0 = blockIdx.x * 64; row0 < G; row0 += gridDim.x * 64) {
        #pragma unroll
        for (int j = 0; j < 8; j++) {
            int r = wy + 8 * j;
            *(float4*)&gs[r][c] = *(const float4*)&g_g[(size_t)(row0 + r) * D + c];
        }
        __syncwarp();
        float4 acc2[8], accP[8];
        float4 bn4 = __ldg((const float4*)&bn[c]);
        float4 bp4 = __ldg((const float4*)&bp[c]);
        #pragma unroll
        for (int j = 0; j < 8; j++) { acc2[j] = bn4; accP[j] = bp4; }
        for (int k = 0; k < D; k++) {
            float4 w2 = __ldg((const float4*)&Wn[(size_t)(D + k) * D + c]);
            float4 wp = __ldg((const float4*)&Wp[(size_t)k * D + c]);
            #pragma unroll
            for (int j = 0; j < 8; j++) {
                float a = gs[wy + 8 * j][k];
                acc2[j].x = fmaf(a, w2.x, acc2[j].x); acc2[j].y = fmaf(a, w2.y, acc2[j].y);
                acc2[j].z = fmaf(a, w2.z, acc2[j].z); acc2[j].w = fmaf(a, w2.w, acc2[j].w);
                accP[j].x = fmaf(a, wp.x, accP[j].x); accP[j].y = fmaf(a, wp.y, accP[j].y);
                accP[j].z = fmaf(a, wp.z, accP[j].z); accP[j].w = fmaf(a, wp.w, accP[j].w);
            }
        }
        #pragma unroll
        for (int j = 0; j < 8; j++) {
            size_t row = row0 + wy + 8 * j;
            *(float4*)&g_gW2[row * D + c] = acc2[j];
            *(float4*)&graph_out[row * D + c] = accP[j];
        }
        __syncwarp();
    }
}

// ---------------- kernel F1: nr = mish(x@Wn1 + gW2[batch]) via bf16x3 HMMA ----------------
// smem: [WH 34816][WL 34816][XH 34816][XL 34816] = 139264
#define F1_SMEM 139264
__global__ __launch_bounds__(256, 1) void k_f1(
    const float* __restrict__ x, const void* __restrict__ batch,
    const float* __restrict__ Wn, float* __restrict__ node_out, int N)
{
    extern __shared__ char sm[];
    const int SM_WH = 0, SM_WL = 34816, SM_XH = 69632, SM_XL = 104448;
    unsigned smb = smem_u32(sm);
    int tid = threadIdx.x, lane = tid & 31, wid = tid >> 5;
    int is64 = d_is64[0];

    conv_w(Wn, sm, SM_WH, SM_WL);      // Wn1 (rows k=0..127) -> [n][k] hi/lo
    __syncthreads();

    int ntiles = N >> 7;
    for (int tile = blockIdx.x; tile < ntiles; tile += gridDim.x) {
        __syncwarp();
        // convert this warp's 16 rows of x into its smem strip
        const float* xb = x + ((size_t)tile * 128 + wid * 16) * D;
        #pragma unroll
        for (int rr = 0; rr < 16; rr++) {
            float4 v = __ldg((const float4*)(xb + rr * D + lane * 4));
            uint2 H, L; split4(v, H, L);
            int row = wid * 16 + rr;
            *(uint2*)(sm + SM_XH + row * STRB + lane * 8) = H;
            *(uint2*)(sm + SM_XL + row * STRB + lane * 8) = L;
        }
        __syncwarp();

        float acc[64];
        #pragma unroll
        for (int i = 0; i < 64; i++) acc[i] = 0.f;
        unsigned ah[4], al[4], bh[4], bl[4];
        unsigned abase = smb + SM_XH + (wid * 16 + (lane & 15)) * STRB + (lane >> 4) * 16;
        unsigned bbase = smb + SM_WH + ((lane & 7) + ((lane >> 4) & 1) * 8) * STRB + ((lane >> 3) & 1) * 16;
        #pragma unroll
        for (int kc = 0; kc < 8; kc++) {
            ldsm4(ah, abase + kc * 32);
            ldsm4(al, abase + kc * 32 + (SM_XL - SM_XH));
            #pragma unroll
            for (int nt2 = 0; nt2 < 8; nt2++) {
                unsigned ba = bbase + nt2 * 16 * STRB + kc * 32;
                ldsm4(bh, ba);
                ldsm4(bl, ba + (SM_WL - SM_WH));
                mma_bf16(acc + 8 * nt2,     ah, bh[0], bh[1]);
                mma_bf16(acc + 8 * nt2,     ah, bl[0], bl[1]);
                mma_bf16(acc + 8 * nt2,     al, bh[0], bh[1]);
                mma_bf16(acc + 8 * nt2 + 4, ah, bh[2], bh[3]);
                mma_bf16(acc + 8 * nt2 + 4, ah, bl[2], bl[3]);
                mma_bf16(acc + 8 * nt2 + 4, al, bh[2], bh[3]);
            }
        }

        // epilogue: + gW2[batch] gather, mish, store
        int rl = lane >> 2, cl = (lane & 3) * 2;
        size_t gr0 = (size_t)tile * 128 + wid * 16 + rl;
        size_t gr1 = gr0 + 8;
        long b0 = ldx(batch, (long)gr0, is64);
        long b1 = ldx(batch, (long)gr1, is64);
        const float* gw0 = g_gW2 + (size_t)b0 * D;
        const float* gw1 = g_gW2 + (size_t)b1 * D;
        float* n0 = node_out + gr0 * D;
        float* n1 = node_out + gr1 * D;
        #pragma unroll
        for (int nt = 0; nt < 16; nt++) {
            int col = nt * 8 + cl;
            float2 g0 = *(const float2*)&gw0[col];
            float2 g1 = *(const float2*)&gw1[col];
            float2 o0 = make_float2(mish1(acc[nt * 4 + 0] + g0.x), mish1(acc[nt * 4 + 1] + g0.y));
            float2 o1 = make_float2(mish1(acc[nt * 4 + 2] + g1.x), mish1(acc[nt * 4 + 3] + g1.y));
            *(float2*)&n0[col] = o0;
            *(float2*)&n1[col] = o1;
        }
    }
}

// ---------------- kernel F2: A=nr@We1, B=nr@We2, self=mish(A+B+be), merged pass ----------------
// smem: [W1H][W1L][W2H][W2L][XH][XL] = 6*34816 = 208896
#define F2_SMEM 208896
__global__ __launch_bounds__(256, 1) void k_f2(
    const float* __restrict__ nr_in, const float* __restrict__ We,
    const float* __restrict__ be,
    float* __restrict__ self_out, int N)
{
    extern __shared__ char sm[];
    const int SM_W1H = 0, SM_W1L = 34816, SM_W2H = 69632, SM_W2L = 104448;
    const int SM_XH = 139264, SM_XL = 174080;
    unsigned smb = smem_u32(sm);
    int tid = threadIdx.x, lane = tid & 31, wid = tid >> 5;

    conv_w(We, sm, SM_W1H, SM_W1L);            // We1 (k rows 0..127)
    conv_w(We + 128 * D, sm, SM_W2H, SM_W2L);  // We2 (k rows 128..255)
    __syncthreads();

    int ntiles = N >> 7;
    for (int tile = blockIdx.x; tile < ntiles; tile += gridDim.x) {
        __syncwarp();
        const float* xb = nr_in + ((size_t)tile * 128 + wid * 16) * D;
        #pragma unroll
        for (int rr = 0; rr < 16; rr++) {
            float4 v = __ldg((const float4*)(xb + rr * D + lane * 4));
            uint2 H, L; split4(v, H, L);
            int row = wid * 16 + rr;
            *(uint2*)(sm + SM_XH + row * STRB + lane * 8) = H;
            *(uint2*)(sm + SM_XL + row * STRB + lane * 8) = L;
        }
        __syncwarp();

        float accA[64], accB[64];
        #pragma unroll
        for (int i = 0; i < 64; i++) { accA[i] = 0.f; accB[i] = 0.f; }
        unsigned ah[4], al[4], bh[4], bl[4];
        unsigned abase = smb + SM_XH + (wid * 16 + (lane & 15)) * STRB + (lane >> 4) * 16;
        unsigned bbase = smb + ((lane & 7) + ((lane >> 4) & 1) * 8) * STRB + ((lane >> 3) & 1) * 16;
        #pragma unroll
        for (int kc = 0; kc < 8; kc++) {
            ldsm4(ah, abase + kc * 32);
            ldsm4(al, abase + kc * 32 + (SM_XL - SM_XH));
            #pragma unroll
            for (int nt2 = 0; nt2 < 8; nt2++) {
                unsigned ba = bbase + nt2 * 16 * STRB + kc * 32;
                ldsm4(bh, ba + SM_W1H);
                ldsm4(bl, ba + SM_W1L);
                mma_bf16(accA + 8 * nt2,     ah, bh[0], bh[1]);
                mma_bf16(accA + 8 * nt2,     ah, bl[0], bl[1]);
                mma_bf16(accA + 8 * nt2,     al, bh[0], bh[1]);
                mma_bf16(accA + 8 * nt2 + 4, ah, bh[2], bh[3]);
                mma_bf16(accA + 8 * nt2 + 4, ah, bl[2], bl[3]);
                mma_bf16(accA + 8 * nt2 + 4, al, bh[2], bh[3]);
                ldsm4(bh, ba + SM_W2H);
                ldsm4(bl, ba + SM_W2L);
                mma_bf16(accB + 8 * nt2,     ah, bh[0], bh[1]);
                mma_bf16(accB + 8 * nt2,     ah, bl[0], bl[1]);
                mma_bf16(accB + 8 * nt2,     al, bh[0], bh[1]);
                mma_bf16(accB + 8 * nt2 + 4, ah, bh[2], bh[3]);
                mma_bf16(accB + 8 * nt2 + 4, ah, bl[2], bl[3]);
                mma_bf16(accB + 8 * nt2 + 4, al, bh[2], bh[3]);
            }
        }

        int rl = lane >> 2, cl = (lane & 3) * 2;
        size_t gr0 = (size_t)tile * 128 + wid * 16 + rl;
        size_t gr1 = gr0 + 8;
        float* A0 = g_A + gr0 * D; float* A1 = g_A + gr1 * D;
        float* B0 = g_B + gr0 * D; float* B1 = g_B + gr1 * D;
        float* S0 = self_out + gr0 * D; float* S1 = self_out + gr1 * D;
        #pragma unroll
        for (int nt = 0; nt < 16; nt++) {
            int col = nt * 8 + cl;
            float2 be2 = *(const float2*)&be[col];
            float2 a0 = make_float2(accA[nt * 4 + 0], accA[nt * 4 + 1]);
            float2 a1 = make_float2(accA[nt * 4 + 2], accA[nt * 4 + 3]);
            float2 b0 = make_float2(accB[nt * 4 + 0], accB[nt * 4 + 1]);
            float2 b1 = make_float2(accB[nt * 4 + 2], accB[nt * 4 + 3]);
            *(float2*)&A0[col] = a0; *(float2*)&A1[col] = a1;
            *(float2*)&B0[col] = b0; *(float2*)&B1[col] = b1;
            float2 s0 = make_float2(mish1(a0.x + b0.x + be2.x), mish1(a0.y + b0.y + be2.y));
            float2 s1 = make_float2(mish1(a1.x + b1.x + be2.x), mish1(a1.y + b1.y + be2.y));
            *(float2*)&S0[col] = s0;
            *(float2*)&S1[col] = s1;
        }
    }
}

// ---------------- kernel 4: edges ----------------
__global__ __launch_bounds__(256) void k_edge(
    const void* __restrict__ ei, const float* __restrict__ be,
    float* __restrict__ edge_out, int E)
{
    int is64 = d_is64[1];
    int lane = threadIdx.x & 31;
    int warp = blockIdx.x * (blockDim.x >> 5) + (threadIdx.x >> 5);
    int nwarps = gridDim.x * (blockDim.x >> 5);
    int c = lane * 4;
    float4 be4 = __ldg((const float4*)&be[c]);
    int pairs = E >> 1;
    for (int p = warp; p < pairs; p += nwarps) {
        long e0 = 2L * p;
        long s0 = ldx(ei, e0, is64);
        long s1 = ldx(ei, e0 + 1, is64);
        long d0 = ldx(ei, (long)E + e0, is64);
        long d1 = ldx(ei, (long)E + e0 + 1, is64);
        float4 a0 = __ldg((const float4*)&g_A[(size_t)s0 * D + c]);
        float4 b0 = __ldg((const float4*)&g_B[(size_t)d0 * D + c]);
        float4 a1 = __ldg((const float4*)&g_A[(size_t)s1 * D + c]);
        float4 b1 = __ldg((const float4*)&g_B[(size_t)d1 * D + c]);
        float4 v0 = mish4(make_float4(a0.x + b0.x + be4.x, a0.y + b0.y + be4.y,
                                      a0.z + b0.z + be4.z, a0.w + b0.w + be4.w));
        float4 v1 = mish4(make_float4(a1.x + b1.x + be4.x, a1.y + b1.y + be4.y,
                                      a1.z + b1.z + be4.z, a1.w + b1.w + be4.w));
        float4 o = make_float4(0.5f * (v0.x + v1.x), 0.5f * (v0.y + v1.y),
                               0.5f * (v0.z + v1.z), 0.5f * (v0.w + v1.w));
        *(float4*)&edge_out[(size_t)p * D + c] = o;
    }
}

// ---------------- launch ----------------
extern "C" void kernel_launch(void* const* d_in, const int* in_sizes, int n_in,
                              void* d_out, int out_size)
{
    const float* x     = (const float*)d_in[0];
    const void*  batch = d_in[1];
    const void*  ei    = d_in[2];
    const float* Wn    = (const float*)d_in[3];
    const float* bn    = (const float*)d_in[4];
    const float* We    = (const float*)d_in[5];
    const float* bee   = (const float*)d_in[6];
    const float* Wp    = (const float*)d_in[7];
    const float* bp    = (const float*)d_in[8];

    int N = in_sizes[0] / D;
    int E = MAXE;

    float* out       = (float*)d_out;
    float* node_out  = out;
    float* self_out  = out + (size_t)N * D;
    float* edge_out  = out + 2 * (size_t)N * D;
    float* graph_out = out + 3 * (size_t)N * D;

    static int init_done = 0;
    if (!init_done) {
        cudaFuncSetAttribute(k_f1, cudaFuncAttributeMaxDynamicSharedMemorySize, F1_SMEM);
        cudaFuncSetAttribute(k_f2, cudaFuncAttributeMaxDynamicSharedMemorySize, F2_SMEM);
        init_done = 1;
    }

    k_detect<<<1, 32>>>((const unsigned*)batch, N, (const unsigned*)ei);
    k_pool<<<NG, 128>>>(x, batch, N);
    k_graphmm<<<NG / 64, 256>>>(Wn, bn, Wp, bp, graph_out, NG);
    k_f1<<<148, 256, F1_SMEM>>>(x, batch, Wn, node_out, N);
    k_f2<<<148, 256, F2_SMEM>>>(node_out, We, bee, self_out, N);
    k_edge<<<2048, 256>>>(ei, bee, edge_out, E);
}